// round 6
// baseline (speedup 1.0000x reference)
#include <cuda_runtime.h>
#include <math.h>

// ---- problem constants ----
#define NB    4
#define LL    512
#define NNODE 2048
#define D0V   640
#define PV    128
#define CV    32
#define HV    4
#define NLV   3
#define RADIN 130
#define HIDV  64
#define R4C   128
#define EMAX  262144
#define GMAX8 (EMAX/8)

typedef unsigned long long ull;

// ---- device scratch (SoA for all degree-1 tensors) ----
__device__ float g_h0  [NNODE*CV];
__device__ float g_h1x [NNODE*CV];
__device__ float g_h1y [NNODE*CV];
__device__ float g_h1z [NNODE*CV];
__device__ float g_q   [NNODE*CV];
__device__ float g_a00 [NNODE*CV];
__device__ float g_a10 [NNODE*CV];
__device__ float g_g01x[NNODE*CV];
__device__ float g_g01y[NNODE*CV];
__device__ float g_g01z[NNODE*CV];
__device__ float g_g11x[2][NNODE*CV];
__device__ float g_g11y[2][NNODE*CV];
__device__ float g_g11z[2][NNODE*CV];
__device__ float g_eft [(size_t)GMAX8*1040];   // transposed ef: [group][i][ei(8)]
__device__ float g_rhat[(size_t)EMAX*3];
__device__ float g_k   [(size_t)EMAX*CV];
__device__ float g_s10 [(size_t)EMAX*CV];
__device__ float g_w11e[(size_t)EMAX*CV];
__device__ float g_logit[(size_t)EMAX*HV];
__device__ int   g_deg   [NNODE];
__device__ int   g_rowptr[NNODE+1];
__device__ int   g_cursor[NNODE];
__device__ int   g_ceidx [EMAX];

// ---- f32x2 helpers ----
__device__ __forceinline__ ull pk2(float a, float b){
    ull r; asm("mov.b64 %0, {%1,%2};" : "=l"(r) : "f"(a), "f"(b)); return r;
}
__device__ __forceinline__ float2 upk(ull v){
    float2 r; asm("mov.b64 {%0,%1}, %2;" : "=f"(r.x), "=f"(r.y) : "l"(v)); return r;
}
__device__ __forceinline__ ull ffma2(ull a, ull b, ull c){
    ull d; asm("fma.rn.f32x2 %0, %1, %2, %3;" : "=l"(d) : "l"(a), "l"(b), "l"(c)); return d;
}
__device__ __forceinline__ float warpsum(float v){
    #pragma unroll
    for (int o = 16; o; o >>= 1) v += __shfl_xor_sync(0xffffffffu, v, o);
    return v;
}

// ---- K0: h0 = seq @ Win0 ; h1 = x * Win1 ; zero g_deg ----
__global__ void k_init_nodes(const float* __restrict__ seq,
                             const float* __restrict__ coords,
                             const float* __restrict__ Win0,
                             const float* __restrict__ Win1){
    extern __shared__ float sm[];
    float* sW   = sm;
    float* sSeq = sm + 20480;
    int tid = threadIdx.x;
    int gi = blockIdx.x*512 + tid;
    if (gi < NNODE) g_deg[gi] = 0;
    for (int i = tid; i < D0V*CV; i += 512) sW[i] = Win0[i];
    int n0 = blockIdx.x * 16;
    for (int i = tid; i < 16*D0V; i += 512) sSeq[i] = seq[(size_t)n0*D0V + i];
    __syncthreads();
    int w = tid >> 5, lane = tid & 31;
    int n = n0 + w;
    const float* srow = sSeq + w*D0V;
    float acc = 0.f;
    #pragma unroll 4
    for (int i = 0; i < D0V; i++) acc += srow[i]*sW[i*CV + lane];
    g_h0[n*CV + lane] = acc;
    float wv = Win1[lane];
    float x0 = coords[n*3+0], x1 = coords[n*3+1], x2 = coords[n*3+2];
    g_h1x[n*CV+lane] = x0*wv;
    g_h1y[n*CV+lane] = x1*wv;
    g_h1z[n*CV+lane] = x2*wv;
}

// ---- K1: geometry + transposed ef + degree count ----
__global__ void k_edge_setup(const float* __restrict__ coords,
                             const float* __restrict__ pair,
                             const float* __restrict__ bppm,
                             const int* __restrict__ src,
                             const int* __restrict__ dst, int E){
    __shared__ float buf[8*1040];
    __shared__ float rbuf[8*8];
    int w = threadIdx.x >> 5, lane = threadIdx.x & 31;
    int nG = (E + 7) >> 3;
    for (int g = blockIdx.x*8 + w; g < nG; g += gridDim.x*8){
        int e0 = g*8;
        float* b = buf + w*1040;
        if (lane < 8){
            int e = e0 + lane;
            float r = 0.f;
            if (e < E){
                int s = src[e], d = dst[e];
                atomicAdd(&g_deg[d], 1);
                float rx = coords[d*3+0]-coords[s*3+0];
                float ry = coords[d*3+1]-coords[s*3+1];
                float rz = coords[d*3+2]-coords[s*3+2];
                r = sqrtf(rx*rx + ry*ry + rz*rz + 1e-12f);
                float inv = 1.f/(r + 1e-8f);
                g_rhat[(size_t)e*3+0] = rx*inv;
                g_rhat[(size_t)e*3+1] = ry*inv;
                g_rhat[(size_t)e*3+2] = rz*inv;
            }
            rbuf[w*8 + lane] = r;
        }
        __syncwarp();
        for (int t = lane; t < 1040; t += 32){
            int ei = t / 130, ii = t - ei*130;
            int e = e0 + ei; float v = 0.f;
            if (e < E){
                int s = src[e], d = dst[e], di = d & (LL-1);
                if (ii < PV)        v = pair[((size_t)s*LL + di)*PV + ii];
                else if (ii == PV)  v = bppm[(size_t)s*LL + di];
                else                v = rbuf[w*8 + ei];
            }
            b[ii*8 + ei] = v;
        }
        __syncwarp();
        for (int t = lane; t < 1040; t += 32) g_eft[(size_t)g*1040 + t] = b[t];
        __syncwarp();
    }
}

// ---- K2: per-node precompute (layer 0) -> writes g11 buffer 0 ----
__global__ void k_node_pre(const float* __restrict__ Wq,
                           const float* __restrict__ Wm00,
                           const float* __restrict__ Wm10,
                           const float* __restrict__ Wm01,
                           const float* __restrict__ Wm11){
    __shared__ float sWq[1024], s00[1024], s10w[1024], s01[1024], s11[1024];
    int tid = threadIdx.x;
    for (int i = tid; i < 1024; i += 256){
        sWq[i] = Wq[i]; s00[i] = Wm00[i]; s10w[i] = Wm10[i];
        s01[i] = Wm01[i]; s11[i] = Wm11[i];
    }
    __syncthreads();
    int w = tid >> 5, lane = tid & 31;
    for (int n = blockIdx.x*8 + w; n < NNODE; n += gridDim.x*8){
        float h  = g_h0 [n*CV + lane];
        float hx = g_h1x[n*CV + lane];
        float hy = g_h1y[n*CV + lane];
        float hz = g_h1z[n*CV + lane];
        float q=0, a00=0, a10=0;
        float g01x=0,g01y=0,g01z=0,g11x=0,g11y=0,g11z=0;
        #pragma unroll 8
        for (int c = 0; c < CV; c++){
            float hc  = __shfl_sync(0xffffffffu, h,  c);
            float hcx = __shfl_sync(0xffffffffu, hx, c);
            float hcy = __shfl_sync(0xffffffffu, hy, c);
            float hcz = __shfl_sync(0xffffffffu, hz, c);
            q   += hc*sWq [c*CV+lane];
            a00 += hc*s00 [c*CV+lane];
            a10 += hc*s10w[c*CV+lane];
            float w01 = s01[c*CV+lane], w11 = s11[c*CV+lane];
            g01x += hcx*w01; g01y += hcy*w01; g01z += hcz*w01;
            g11x += hcx*w11; g11y += hcy*w11; g11z += hcz*w11;
        }
        g_q  [n*CV+lane] = q;
        g_a00[n*CV+lane] = a00;
        g_a10[n*CV+lane] = a10;
        g_g01x[n*CV+lane]=g01x; g_g01y[n*CV+lane]=g01y; g_g01z[n*CV+lane]=g01z;
        g_g11x[0][n*CV+lane]=g11x; g_g11y[0][n*CV+lane]=g11y; g_g11z[0][n*CV+lane]=g11z;
    }
}

// ---- CSR scan + fill ----
__global__ void k_scan(int E){
    __shared__ int s[NNODE];
    int t = threadIdx.x;
    s[t] = g_deg[t]; s[t+1024] = g_deg[t+1024];
    __syncthreads();
    for (int off = 1; off < NNODE; off <<= 1){
        int v0 = (t >= off) ? s[t-off] : 0;
        int i1 = t + 1024;
        int v1 = (i1 >= off) ? s[i1-off] : 0;
        __syncthreads();
        s[t] += v0; s[i1] += v1;
        __syncthreads();
    }
    g_rowptr[t+1]    = s[t];
    g_rowptr[t+1025] = s[t+1024];
    if (t == 0) g_rowptr[0] = 0;
    g_cursor[t]      = (t == 0) ? 0 : s[t-1];
    g_cursor[t+1024] = s[t+1023];
}
__global__ void k_fill(const int* __restrict__ dst, int E){
    int i = blockIdx.x*256 + threadIdx.x;
    if (i < E){
        int p = atomicAdd(&g_cursor[dst[i]], 1);
        g_ceidx[p] = i;
    }
}

// ---- K3: radial MLP + messages + logits ; 8 edges/warp, f32x2 ----
#define P1_HIDOFF 16512
#define P1_SMEMF  (P1_HIDOFF + 8*512)
#define P1_SMEMB  (P1_SMEMF*4)

__global__ void __launch_bounds__(256, 2)
k_edge_pass1(const int* __restrict__ esrc,
             const int* __restrict__ edst,
             const float* __restrict__ Wr1,
             const float* __restrict__ br1,
             const float* __restrict__ Wr2,
             const float* __restrict__ br2, int E, int rb){
    extern __shared__ float sm[];
    float* sWr1 = sm;
    float* sWr2 = sm + 8320;
    int tid = threadIdx.x;
    for (int i = tid; i < 8320; i += 256) sWr1[i] = Wr1[i];
    for (int t = tid; t < 8192; t += 256){
        int q = t >> 2, m = t & 3, j = q >> 5, lc = q & 31;
        sWr2[t] = Wr2[j*128 + m*32 + lc];
    }
    __syncthreads();

    int w = tid >> 5, lane = tid & 31;
    float* myhid = sm + P1_HIDOFF + w*512;

    float2 b1 = ((const float2*)br1)[lane];
    ull bb0 = pk2(b1.x, b1.x), bb1 = pk2(b1.y, b1.y);
    ull B0 = pk2(br2[lane],    br2[lane]);
    ull B1 = pk2(br2[32+lane], br2[32+lane]);
    ull B2 = pk2(br2[64+lane], br2[64+lane]);
    ull B3 = pk2(br2[96+lane], br2[96+lane]);

    int nG = (E + 7) >> 3;
    for (int g = blockIdx.x*8 + w; g < nG; g += gridDim.x*8){
        int e0 = g*8;
        int eCnt = E - e0; if (eCnt > 8) eCnt = 8;
        const ulonglong2* efv = (const ulonglong2*)(g_eft + (size_t)g*1040);

        // batched index/rhat loads (coalesced-ish, then shfl-broadcast)
        int  sreg = (lane < eCnt) ? esrc[e0 + lane] : 0;
        int  dreg = (lane < eCnt) ? edst[e0 + lane] : 0;
        float rreg = (lane < eCnt*3) ? g_rhat[(size_t)e0*3 + lane] : 0.f;

        // ---- layer1: 130 -> 64
        ull a00=bb0,a01=bb0,a02=bb0,a03=bb0;
        ull a10=bb1,a11=bb1,a12=bb1,a13=bb1;
        const float2* w1v = (const float2*)sWr1;
        #pragma unroll 4
        for (int i = 0; i < 130; i++){
            float2 wv = w1v[i*32 + lane];
            ull wx = pk2(wv.x, wv.x), wy = pk2(wv.y, wv.y);
            ulonglong2 pA = efv[2*i];
            ulonglong2 pB = efv[2*i+1];
            a00 = ffma2(pA.x, wx, a00); a01 = ffma2(pA.y, wx, a01);
            a02 = ffma2(pB.x, wx, a02); a03 = ffma2(pB.y, wx, a03);
            a10 = ffma2(pA.x, wy, a10); a11 = ffma2(pA.y, wy, a11);
            a12 = ffma2(pB.x, wy, a12); a13 = ffma2(pB.y, wy, a13);
        }
        {
            float4* h4 = (float4*)myhid;
            float2 u0=upk(a00), u1=upk(a01), u2=upk(a02), u3=upk(a03);
            h4[(2*lane)*2+0] = make_float4(fmaxf(u0.x,0.f),fmaxf(u0.y,0.f),fmaxf(u1.x,0.f),fmaxf(u1.y,0.f));
            h4[(2*lane)*2+1] = make_float4(fmaxf(u2.x,0.f),fmaxf(u2.y,0.f),fmaxf(u3.x,0.f),fmaxf(u3.y,0.f));
            float2 v0=upk(a10), v1=upk(a11), v2=upk(a12), v3=upk(a13);
            h4[(2*lane+1)*2+0] = make_float4(fmaxf(v0.x,0.f),fmaxf(v0.y,0.f),fmaxf(v1.x,0.f),fmaxf(v1.y,0.f));
            h4[(2*lane+1)*2+1] = make_float4(fmaxf(v2.x,0.f),fmaxf(v2.y,0.f),fmaxf(v3.x,0.f),fmaxf(v3.y,0.f));
        }
        __syncwarp();

        // ---- layer2: 64 -> 128
        ull o[4][4];
        #pragma unroll
        for (int p = 0; p < 4; p++){ o[0][p]=B0; o[1][p]=B1; o[2][p]=B2; o[3][p]=B3; }
        const float4*     w2v  = (const float4*)sWr2;
        const ulonglong2* hidv = (const ulonglong2*)myhid;
        #pragma unroll 2
        for (int j = 0; j < 64; j++){
            float4 wv = w2v[j*32 + lane];
            ull w0 = pk2(wv.x,wv.x), w1 = pk2(wv.y,wv.y), w2 = pk2(wv.z,wv.z), w3 = pk2(wv.w,wv.w);
            ulonglong2 hA = hidv[j*2];
            ulonglong2 hB = hidv[j*2+1];
            o[0][0]=ffma2(hA.x,w0,o[0][0]); o[0][1]=ffma2(hA.y,w0,o[0][1]);
            o[0][2]=ffma2(hB.x,w0,o[0][2]); o[0][3]=ffma2(hB.y,w0,o[0][3]);
            o[1][0]=ffma2(hA.x,w1,o[1][0]); o[1][1]=ffma2(hA.y,w1,o[1][1]);
            o[1][2]=ffma2(hB.x,w1,o[1][2]); o[1][3]=ffma2(hB.y,w1,o[1][3]);
            o[2][0]=ffma2(hA.x,w2,o[2][0]); o[2][1]=ffma2(hA.y,w2,o[2][1]);
            o[2][2]=ffma2(hB.x,w2,o[2][2]); o[2][3]=ffma2(hB.y,w2,o[2][3]);
            o[3][0]=ffma2(hA.x,w3,o[3][0]); o[3][1]=ffma2(hA.y,w3,o[3][1]);
            o[3][2]=ffma2(hB.x,w3,o[3][2]); o[3][3]=ffma2(hB.y,w3,o[3][3]);
        }

        // ---- per-edge tail (SoA coalesced gathers)
        const float* g01xp = g_g01x;  // hint uniform base
        #pragma unroll
        for (int ei = 0; ei < 8; ei++){
            if (ei >= eCnt) break;
            int e = e0 + ei;
            int p = ei >> 1;
            float2 q0 = upk(o[0][p]), q1 = upk(o[1][p]), q2 = upk(o[2][p]), q3 = upk(o[3][p]);
            float r0 = (ei&1)? q0.y : q0.x;
            float r1 = (ei&1)? q1.y : q1.x;
            float r2 = (ei&1)? q2.y : q2.x;
            float r3 = (ei&1)? q3.y : q3.x;
            int s = __shfl_sync(0xffffffffu, sreg, ei);
            int d = __shfl_sync(0xffffffffu, dreg, ei);
            float rx = __shfl_sync(0xffffffffu, rreg, ei*3+0);
            float ry = __shfl_sync(0xffffffffu, rreg, ei*3+1);
            float rz = __shfl_sync(0xffffffffu, rreg, ei*3+2);
            int sc = s*CV + lane;
            float gdot = g01xp[sc]*rx + g_g01y[sc]*ry + g_g01z[sc]*rz;
            float kc = r0*g_a00[sc] + r1*gdot;
            size_t ec = (size_t)e*CV + lane;
            g_k[ec]    = kc;
            g_s10[ec]  = r2*g_a10[sc];
            g_w11e[ec] = r3;
            float pq = g_q[d*CV+lane]*kc;
            pq += __shfl_down_sync(0xffffffffu, pq, 4);
            pq += __shfl_down_sync(0xffffffffu, pq, 2);
            pq += __shfl_down_sync(0xffffffffu, pq, 1);
            if ((lane & 7) == 0)
                g_logit[(size_t)e*HV + (lane>>3)] = pq * 0.3535533906f;
        }
    }
}

// ---- K4: softmax + aggregation + update + norms (+ fused pre/final) ----
__global__ void k_node_agg(const int* __restrict__ esrc,
                           const float* __restrict__ Wself0,
                           const float* __restrict__ Wself1,
                           const float* __restrict__ gamma0,
                           const float* __restrict__ beta0,
                           const float* __restrict__ gamma1,
                           const float* __restrict__ WqN,
                           const float* __restrict__ W00N,
                           const float* __restrict__ W10N,
                           const float* __restrict__ W01N,
                           const float* __restrict__ W11N,
                           int do_pre,
                           const float* __restrict__ Wout,
                           const float* __restrict__ coords,
                           float* __restrict__ out,
                           int do_final, int rb){
    __shared__ float sW0[1024], sW1[1024];
    __shared__ float sPq[1024], sP00[1024], sP10[1024], sP01[1024], sP11[1024];
    int tid = threadIdx.x;
    for (int i = tid; i < 1024; i += 256){ sW0[i] = Wself0[i]; sW1[i] = Wself1[i]; }
    if (do_pre){
        for (int i = tid; i < 1024; i += 256){
            sPq[i] = WqN[i]; sP00[i] = W00N[i]; sP10[i] = W10N[i];
            sP01[i] = W01N[i]; sP11[i] = W11N[i];
        }
    }
    __syncthreads();
    const float* g11rx = g_g11x[rb];
    const float* g11ry = g_g11y[rb];
    const float* g11rz = g_g11z[rb];
    float* g11wx = g_g11x[rb^1];
    float* g11wy = g_g11y[rb^1];
    float* g11wz = g_g11z[rb^1];
    int w = tid >> 5, lane = tid & 31;
    for (int n = blockIdx.x*8 + w; n < NNODE; n += gridDim.x*8){
        int rp = g_rowptr[n], deg = g_rowptr[n+1] - rp;
        float mx = -1e30f;
        for (int j0 = 0; j0 < deg; j0 += 8){
            int j = j0 + (lane >> 2);
            if (j < deg){
                int e = g_ceidx[rp + j];
                mx = fmaxf(mx, g_logit[(size_t)e*HV + (lane & 3)]);
            }
        }
        mx = fmaxf(mx, __shfl_xor_sync(0xffffffffu, mx, 4));
        mx = fmaxf(mx, __shfl_xor_sync(0xffffffffu, mx, 8));
        mx = fmaxf(mx, __shfl_xor_sync(0xffffffffu, mx, 16));
        if (mx < -1e29f) mx = 0.f;
        float den = 0.f;
        for (int j0 = 0; j0 < deg; j0 += 8){
            int j = j0 + (lane >> 2);
            if (j < deg){
                int e = g_ceidx[rp + j];
                den += expf(g_logit[(size_t)e*HV + (lane & 3)] - mx);
            }
        }
        den += __shfl_xor_sync(0xffffffffu, den, 4);
        den += __shfl_xor_sync(0xffffffffu, den, 8);
        den += __shfl_xor_sync(0xffffffffu, den, 16);
        float mxh  = __shfl_sync(0xffffffffu, mx,  lane >> 3);
        float dinv = 1.f / (__shfl_sync(0xffffffffu, den, lane >> 3) + 1e-9f);
        float a0=0.f, ax=0.f, ay=0.f, az=0.f;
        for (int j = 0; j < deg; j++){
            int e = g_ceidx[rp + j];
            float alpha = expf(g_logit[(size_t)e*HV + (lane>>3)] - mxh) * dinv;
            size_t ec = (size_t)e*CV + lane;
            float kc = g_k[ec];
            a0 += alpha * kc;
            float s10 = g_s10[ec], w11 = g_w11e[ec];
            float rx = g_rhat[(size_t)e*3+0];
            float ry = g_rhat[(size_t)e*3+1];
            float rz = g_rhat[(size_t)e*3+2];
            int s  = esrc[e];
            int sc = s*CV + lane;
            ax += alpha * (w11*g11rx[sc] + s10*rx);
            ay += alpha * (w11*g11ry[sc] + s10*ry);
            az += alpha * (w11*g11rz[sc] + s10*rz);
        }
        float nh0 = g_h0 [n*CV + lane];
        float x   = g_h1x[n*CV + lane];
        float y   = g_h1y[n*CV + lane];
        float z   = g_h1z[n*CV + lane];
        #pragma unroll 8
        for (int c = 0; c < CV; c++){
            float b0 = __shfl_sync(0xffffffffu, a0, c);
            float bx = __shfl_sync(0xffffffffu, ax, c);
            float by = __shfl_sync(0xffffffffu, ay, c);
            float bz = __shfl_sync(0xffffffffu, az, c);
            float w0 = sW0[c*CV+lane], w1 = sW1[c*CV+lane];
            nh0 += b0*w0;
            x += bx*w1; y += by*w1; z += bz*w1;
        }
        float mu  = warpsum(nh0) * (1.f/32.f);
        float dv  = nh0 - mu;
        float var = warpsum(dv*dv) * (1.f/32.f);
        float h0new = dv*rsqrtf(var + 1e-5f)*gamma0[lane] + beta0[lane];
        g_h0[n*CV+lane] = h0new;
        float nrm  = sqrtf(x*x + y*y + z*z + 1e-12f);
        float mun  = warpsum(nrm) * (1.f/32.f);
        float dn   = nrm - mun;
        float varn = warpsum(dn*dn) * (1.f/32.f);
        float nln  = dn*rsqrtf(varn + 1e-5f)*gamma1[lane];
        float sc   = nln / (nrm + 1e-8f);
        float hx = x*sc, hy = y*sc, hz = z*sc;
        g_h1x[n*CV+lane] = hx;
        g_h1y[n*CV+lane] = hy;
        g_h1z[n*CV+lane] = hz;

        if (do_pre){
            float q=0, p00=0, p10=0;
            float g01x=0,g01y=0,g01z=0,g11x=0,g11y=0,g11z=0;
            #pragma unroll 8
            for (int c = 0; c < CV; c++){
                float hc  = __shfl_sync(0xffffffffu, h0new, c);
                float hcx = __shfl_sync(0xffffffffu, hx, c);
                float hcy = __shfl_sync(0xffffffffu, hy, c);
                float hcz = __shfl_sync(0xffffffffu, hz, c);
                q   += hc*sPq [c*CV+lane];
                p00 += hc*sP00[c*CV+lane];
                p10 += hc*sP10[c*CV+lane];
                float w01 = sP01[c*CV+lane], w11 = sP11[c*CV+lane];
                g01x += hcx*w01; g01y += hcy*w01; g01z += hcz*w01;
                g11x += hcx*w11; g11y += hcy*w11; g11z += hcz*w11;
            }
            g_q  [n*CV+lane] = q;
            g_a00[n*CV+lane] = p00;
            g_a10[n*CV+lane] = p10;
            g_g01x[n*CV+lane]=g01x; g_g01y[n*CV+lane]=g01y; g_g01z[n*CV+lane]=g01z;
            g11wx[n*CV+lane]=g11x; g11wy[n*CV+lane]=g11y; g11wz[n*CV+lane]=g11z;
        }
        if (do_final){
            float wo = Wout[lane];
            float dx = warpsum(hx*wo);
            float dy = warpsum(hy*wo);
            float dz = warpsum(hz*wo);
            if (lane == 0){
                out[n*3+0] = coords[n*3+0] + dx;
                out[n*3+1] = coords[n*3+1] + dy;
                out[n*3+2] = coords[n*3+2] + dz;
            }
        }
    }
}

extern "C" void kernel_launch(void* const* d_in, const int* in_sizes, int n_in,
                              void* d_out, int out_size){
    const float* seq    = (const float*)d_in[0];
    const float* pair   = (const float*)d_in[1];
    const float* bppm   = (const float*)d_in[2];
    const float* coords = (const float*)d_in[3];
    const int*   esrc   = (const int*)  d_in[4];
    const int*   edst   = (const int*)  d_in[5];
    const float* Win0   = (const float*)d_in[6];
    const float* Win1   = (const float*)d_in[7];
    const float* Wr1    = (const float*)d_in[8];
    const float* br1    = (const float*)d_in[9];
    const float* Wr2    = (const float*)d_in[10];
    const float* br2    = (const float*)d_in[11];
    const float* Wm00   = (const float*)d_in[12];
    const float* Wm01   = (const float*)d_in[13];
    const float* Wm10   = (const float*)d_in[14];
    const float* Wm11   = (const float*)d_in[15];
    const float* Wq     = (const float*)d_in[16];
    const float* Wself0 = (const float*)d_in[17];
    const float* Wself1 = (const float*)d_in[18];
    const float* gamma0 = (const float*)d_in[19];
    const float* beta0  = (const float*)d_in[20];
    const float* gamma1 = (const float*)d_in[21];
    const float* Wout   = (const float*)d_in[22];

    int E = in_sizes[4];
    if (E > EMAX) E = EMAX;
    int nG8 = (E + 7) >> 3;

    cudaFuncSetAttribute(k_edge_pass1,
        cudaFuncAttributeMaxDynamicSharedMemorySize, P1_SMEMB);
    cudaFuncSetAttribute(k_init_nodes,
        cudaFuncAttributeMaxDynamicSharedMemorySize, (20480+16*D0V)*4);

    // pass1 (layer 0) is launch #4 -> ncu captures it
    k_init_nodes<<<128, 512, (20480+16*D0V)*4>>>(seq, coords, Win0, Win1);
    k_edge_setup<<<(nG8+7)/8, 256>>>(coords, pair, bppm, esrc, edst, E);
    k_node_pre<<<128, 256>>>(Wq, Wm00, Wm10, Wm01, Wm11);
    k_edge_pass1<<<296, 256, P1_SMEMB>>>(esrc, edst, Wr1, br1, Wr2, br2, E, 0);

    k_scan<<<1, 1024>>>(E);
    k_fill<<<(E+255)/256, 256>>>(edst, E);

    for (int l = 0; l < NLV; l++){
        int lp = l + 1;
        int rb = l & 1;
        int do_pre = (l < NLV-1);
        int do_fin = (l == NLV-1);
        if (l > 0)
            k_edge_pass1<<<296, 256, P1_SMEMB>>>(esrc, edst,
                Wr1 + l*RADIN*HIDV, br1 + l*HIDV, Wr2 + l*HIDV*R4C, br2 + l*R4C, E, rb);
        k_node_agg<<<256, 256>>>(esrc,
            Wself0 + l*CV*CV, Wself1 + l*CV*CV,
            gamma0 + l*CV, beta0 + l*CV, gamma1 + l*CV,
            Wq + (do_pre ? lp*CV*CV : 0), Wm00 + (do_pre ? lp*CV*CV : 0),
            Wm10 + (do_pre ? lp*CV*CV : 0), Wm01 + (do_pre ? lp*CV*CV : 0),
            Wm11 + (do_pre ? lp*CV*CV : 0), do_pre,
            Wout, coords, (float*)d_out, do_fin, rb);
    }
}

// round 9
// speedup vs baseline: 1.3510x; 1.3510x over previous
#include <cuda_runtime.h>
#include <cuda_bf16.h>
#include <math.h>
#include <stdint.h>

// ---- problem constants ----
#define NB    4
#define LL    512
#define NNODE 2048
#define D0V   640
#define PV    128
#define CV    32
#define HV    4
#define NLV   3
#define RADIN 130
#define HIDV  64
#define R4C   128
#define EMAX  262144

typedef unsigned long long ull;

// ---- device scratch ----
__device__ float g_h0  [NNODE*CV];
__device__ float g_h1x [NNODE*CV];
__device__ float g_h1y [NNODE*CV];
__device__ float g_h1z [NNODE*CV];
__device__ float g_q   [NNODE*CV];
__device__ float g_a00 [NNODE*CV];
__device__ float g_a10 [NNODE*CV];
__device__ float g_g01x[NNODE*CV];
__device__ float g_g01y[NNODE*CV];
__device__ float g_g01z[NNODE*CV];
__device__ float g_g11x[2][NNODE*CV];
__device__ float g_g11y[2][NNODE*CV];
__device__ float g_g11z[2][NNODE*CV];
// A tiles in mma fragment-major order: [m-chunk(16 edges)][k-step(8)][lane(32)][4xb32]
__device__ unsigned char g_a1h[(size_t)(EMAX/16)*4096];
__device__ unsigned char g_a1l[(size_t)(EMAX/16)*4096];
__device__ float2 g_bpr[EMAX];
__device__ float g_rhat[(size_t)EMAX*3];
__device__ float g_k   [(size_t)EMAX*CV];
__device__ float g_s10 [(size_t)EMAX*CV];
__device__ float g_w11e[(size_t)EMAX*CV];
__device__ float g_logit[(size_t)EMAX*HV];
__device__ int   g_deg   [NNODE];
__device__ int   g_rowptr[NNODE+1];
__device__ int   g_cursor[NNODE];
__device__ int   g_ceidx [EMAX];

// ---- helpers ----
__device__ __forceinline__ float warpsum(float v){
    #pragma unroll
    for (int o = 16; o; o >>= 1) v += __shfl_xor_sync(0xffffffffu, v, o);
    return v;
}
__device__ __forceinline__ uint32_t bf16pack(float a, float b){
    __nv_bfloat162 t = __floats2bfloat162_rn(a, b);
    return *(uint32_t*)&t;
}
__device__ __forceinline__ uint32_t bf16lopack(float a, float ha, float b, float hb){
    __nv_bfloat162 t = __floats2bfloat162_rn(a - ha, b - hb);
    return *(uint32_t*)&t;
}
__device__ __forceinline__ float bf16hi(float a){
    return __bfloat162float(__float2bfloat16_rn(a));
}

#define MMA_BF16(c, ax, ay, az, aw, b0, b1) \
    asm volatile("mma.sync.aligned.m16n8k16.row.col.f32.bf16.bf16.f32 " \
        "{%0,%1,%2,%3}, {%4,%5,%6,%7}, {%8,%9}, {%0,%1,%2,%3};" \
        : "+f"((c)[0]), "+f"((c)[1]), "+f"((c)[2]), "+f"((c)[3]) \
        : "r"(ax), "r"(ay), "r"(az), "r"(aw), "r"(b0), "r"(b1))

// ---- K0: h0 = seq @ Win0 ; h1 = x * Win1 ; zero g_deg ----
__global__ void k_init_nodes(const float* __restrict__ seq,
                             const float* __restrict__ coords,
                             const float* __restrict__ Win0,
                             const float* __restrict__ Win1){
    extern __shared__ float sm[];
    float* sW   = sm;
    float* sSeq = sm + 20480;
    int tid = threadIdx.x;
    int gi = blockIdx.x*512 + tid;
    if (gi < NNODE) g_deg[gi] = 0;
    for (int i = tid; i < D0V*CV; i += 512) sW[i] = Win0[i];
    int n0 = blockIdx.x * 16;
    for (int i = tid; i < 16*D0V; i += 512) sSeq[i] = seq[(size_t)n0*D0V + i];
    __syncthreads();
    int w = tid >> 5, lane = tid & 31;
    int n = n0 + w;
    const float* srow = sSeq + w*D0V;
    float acc = 0.f;
    #pragma unroll 4
    for (int i = 0; i < D0V; i++) acc += srow[i]*sW[i*CV + lane];
    g_h0[n*CV + lane] = acc;
    float wv = Win1[lane];
    g_h1x[n*CV+lane] = coords[n*3+0]*wv;
    g_h1y[n*CV+lane] = coords[n*3+1]*wv;
    g_h1z[n*CV+lane] = coords[n*3+2]*wv;
}

// ---- K1: geometry + fragment-major bf16 hi/lo A tiles + (bppm,r) + deg ----
__global__ void k_edge_setup(const float* __restrict__ coords,
                             const float* __restrict__ pair,
                             const float* __restrict__ bppm,
                             const int* __restrict__ src,
                             const int* __restrict__ dst, int E){
    int w = threadIdx.x >> 5, lane = threadIdx.x & 31;
    for (int e = blockIdx.x*8 + w; e < E; e += gridDim.x*8){
        int s = src[e], d = dst[e];
        int di = d & (LL-1);
        if (lane == 0){
            atomicAdd(&g_deg[d], 1);
            float rx = coords[d*3+0]-coords[s*3+0];
            float ry = coords[d*3+1]-coords[s*3+1];
            float rz = coords[d*3+2]-coords[s*3+2];
            float r  = sqrtf(rx*rx + ry*ry + rz*rz + 1e-12f);
            float inv = 1.f/(r + 1e-8f);
            g_rhat[(size_t)e*3+0] = rx*inv;
            g_rhat[(size_t)e*3+1] = ry*inv;
            g_rhat[(size_t)e*3+2] = rz*inv;
            g_bpr[e] = make_float2(bppm[(size_t)s*LL + di], r);
        }
        // lane covers k = 4*lane .. 4*lane+3 of pair features
        float4 pv = ((const float4*)(pair + ((size_t)s*LL + di)*PV))[lane];
        float h0 = bf16hi(pv.x), h1 = bf16hi(pv.y), h2 = bf16hi(pv.z), h3 = bf16hi(pv.w);
        uint32_t w0h = bf16pack(pv.x, pv.y);           // takes hi of each
        uint32_t w1h = bf16pack(pv.z, pv.w);
        uint32_t w0l = bf16pack(pv.x - h0, pv.y - h1);
        uint32_t w1l = bf16pack(pv.z - h2, pv.w - h3);
        int mc = e >> 4, r = e & 15;
        int kk = lane >> 2, m4 = lane & 3;
        int regb = (m4 < 2) ? 0 : 2;
        int reg  = regb + ((r < 8) ? 0 : 1);
        int lt01 = (r & 7)*4 + (m4 & 1)*2;
        int lt23 = lt01 + 1;
        size_t base = (size_t)mc*4096 + (size_t)kk*512;
        *(uint32_t*)(g_a1h + base + lt01*16 + reg*4) = w0h;
        *(uint32_t*)(g_a1h + base + lt23*16 + reg*4) = w1h;
        *(uint32_t*)(g_a1l + base + lt01*16 + reg*4) = w0l;
        *(uint32_t*)(g_a1l + base + lt23*16 + reg*4) = w1l;
    }
}

// ---- K2: per-node precompute (layer 0) ----
__global__ void k_node_pre(const float* __restrict__ Wq,
                           const float* __restrict__ Wm00,
                           const float* __restrict__ Wm10,
                           const float* __restrict__ Wm01,
                           const float* __restrict__ Wm11){
    __shared__ float sWq[1024], s00[1024], s10w[1024], s01[1024], s11[1024];
    int tid = threadIdx.x;
    for (int i = tid; i < 1024; i += 256){
        sWq[i] = Wq[i]; s00[i] = Wm00[i]; s10w[i] = Wm10[i];
        s01[i] = Wm01[i]; s11[i] = Wm11[i];
    }
    __syncthreads();
    int w = tid >> 5, lane = tid & 31;
    for (int n = blockIdx.x*8 + w; n < NNODE; n += gridDim.x*8){
        float h  = g_h0 [n*CV + lane];
        float hx = g_h1x[n*CV + lane];
        float hy = g_h1y[n*CV + lane];
        float hz = g_h1z[n*CV + lane];
        float q=0, a00=0, a10=0;
        float g01x=0,g01y=0,g01z=0,g11x=0,g11y=0,g11z=0;
        #pragma unroll 8
        for (int c = 0; c < CV; c++){
            float hc  = __shfl_sync(0xffffffffu, h,  c);
            float hcx = __shfl_sync(0xffffffffu, hx, c);
            float hcy = __shfl_sync(0xffffffffu, hy, c);
            float hcz = __shfl_sync(0xffffffffu, hz, c);
            q   += hc*sWq [c*CV+lane];
            a00 += hc*s00 [c*CV+lane];
            a10 += hc*s10w[c*CV+lane];
            float w01 = s01[c*CV+lane], w11 = s11[c*CV+lane];
            g01x += hcx*w01; g01y += hcy*w01; g01z += hcz*w01;
            g11x += hcx*w11; g11y += hcy*w11; g11z += hcz*w11;
        }
        g_q  [n*CV+lane] = q;
        g_a00[n*CV+lane] = a00;
        g_a10[n*CV+lane] = a10;
        g_g01x[n*CV+lane]=g01x; g_g01y[n*CV+lane]=g01y; g_g01z[n*CV+lane]=g01z;
        g_g11x[0][n*CV+lane]=g11x; g_g11y[0][n*CV+lane]=g11y; g_g11z[0][n*CV+lane]=g11z;
    }
}

// ---- CSR scan + fill ----
__global__ void k_scan(int E){
    __shared__ int s[NNODE];
    int t = threadIdx.x;
    s[t] = g_deg[t]; s[t+1024] = g_deg[t+1024];
    __syncthreads();
    for (int off = 1; off < NNODE; off <<= 1){
        int v0 = (t >= off) ? s[t-off] : 0;
        int i1 = t + 1024;
        int v1 = (i1 >= off) ? s[i1-off] : 0;
        __syncthreads();
        s[t] += v0; s[i1] += v1;
        __syncthreads();
    }
    g_rowptr[t+1]    = s[t];
    g_rowptr[t+1025] = s[t+1024];
    if (t == 0) g_rowptr[0] = 0;
    g_cursor[t]      = (t == 0) ? 0 : s[t-1];
    g_cursor[t+1024] = s[t+1023];
}
__global__ void k_fill(const int* __restrict__ dst, int E){
    int i = blockIdx.x*256 + threadIdx.x;
    if (i < E){
        int p = atomicAdd(&g_cursor[dst[i]], 1);
        g_ceidx[p] = i;
    }
}

// ===================== mma.sync pass1 =====================
// smem float offsets
#define SO_B1H  0        // 4096 u32
#define SO_B1L  4096
#define SO_B2H  8192
#define SO_B2L  12288
#define SO_BR1  16384    // 64 f
#define SO_BR2  16448    // 128 f
#define SO_W1T  16576    // 128 f
#define SO_TBUF 16704    // 64*132 f
#define SM_FLOATS (16704 + 64*132)
#define SM_BYTES  (SM_FLOATS*4)

__global__ void __launch_bounds__(128, 2)
k_mma_pass1(const int* __restrict__ esrc,
            const int* __restrict__ edst,
            const float* __restrict__ Wr1,
            const float* __restrict__ br1,
            const float* __restrict__ Wr2,
            const float* __restrict__ br2, int E){
    extern __shared__ float sm[];
    uint32_t* sB1h = (uint32_t*)(sm + SO_B1H);
    uint32_t* sB1l = (uint32_t*)(sm + SO_B1L);
    uint32_t* sB2h = (uint32_t*)(sm + SO_B2H);
    uint32_t* sB2l = (uint32_t*)(sm + SO_B2L);
    float* sbr1 = sm + SO_BR1;
    float* sbr2 = sm + SO_BR2;
    float* sW1t = sm + SO_W1T;
    float* tbuf = sm + SO_TBUF;
    int tid = threadIdx.x, w = tid >> 5, lane = tid & 31;

    // ---- stage B fragments (bf16 hi/lo) ----
    for (int idx = tid; idx < 4096; idx += 128){
        int reg = idx & 1, lf = (idx >> 1) & 31, nt = (idx >> 6) & 7, kk = idx >> 9;
        int k = kk*16 + (lf & 3)*2 + reg*8;
        int n = nt*8 + (lf >> 2);
        float v0 = Wr1[k*64 + n], v1 = Wr1[(k+1)*64 + n];
        float h0 = bf16hi(v0), h1 = bf16hi(v1);
        sB1h[idx] = bf16pack(v0, v1);
        sB1l[idx] = bf16pack(v0 - h0, v1 - h1);
    }
    for (int idx = tid; idx < 4096; idx += 128){
        int reg = idx & 1, lf = (idx >> 1) & 31, nt = (idx >> 6) & 15, kk = idx >> 10;
        int k = kk*16 + (lf & 3)*2 + reg*8;
        int n = nt*8 + (lf >> 2);
        float v0 = Wr2[k*128 + n], v1 = Wr2[(k+1)*128 + n];
        float h0 = bf16hi(v0), h1 = bf16hi(v1);
        sB2h[idx] = bf16pack(v0, v1);
        sB2l[idx] = bf16pack(v0 - h0, v1 - h1);
    }
    if (tid < 64){
        sbr1[tid] = br1[tid];
        sW1t[tid]      = Wr1[128*64 + tid];
        sW1t[64 + tid] = Wr1[129*64 + tid];
    }
    if (tid < 128) sbr2[tid] = br2[tid];
    __syncthreads();

    int nT = (E + 63) >> 6;
    int r0 = lane >> 2;
    int cb = (lane & 3)*2;

    for (int tt = blockIdx.x; tt < nT; tt += gridDim.x){
        int mc = tt*4 + w;                     // this warp's m-chunk (16 edges)
        size_t abase = (size_t)mc*4096 + lane*16;

        // ---- GEMM1: [16,128] x [128,64] hi/lo split ----
        float acc1[8][4];
        #pragma unroll
        for (int n = 0; n < 8; n++){ acc1[n][0]=0; acc1[n][1]=0; acc1[n][2]=0; acc1[n][3]=0; }
        #pragma unroll
        for (int kk = 0; kk < 8; kk++){
            uint4 Ah = *(const uint4*)(g_a1h + abase + kk*512);
            uint4 Al = *(const uint4*)(g_a1l + abase + kk*512);
            #pragma unroll
            for (int n = 0; n < 8; n++){
                int bi = ((kk*8 + n)*32 + lane)*2;
                uint32_t bh0 = sB1h[bi], bh1 = sB1h[bi+1];
                uint32_t bl0 = sB1l[bi], bl1 = sB1l[bi+1];
                MMA_BF16(acc1[n], Ah.x, Ah.y, Ah.z, Ah.w, bh0, bh1);
                MMA_BF16(acc1[n], Ah.x, Ah.y, Ah.z, Ah.w, bl0, bl1);
                MMA_BF16(acc1[n], Al.x, Al.y, Al.z, Al.w, bh0, bh1);
            }
        }

        // ---- epilogue1: +bias +exact(bppm,r) relu; build A2 fragments ----
        int eg0 = mc*16 + r0, eg1 = eg0 + 8;
        float2 b0 = g_bpr[eg0];
        float2 b1 = g_bpr[eg1];
        uint32_t A2h[4][4], A2l[4][4];
        #pragma unroll
        for (int n = 0; n < 8; n++){
            int u0 = n*8 + cb, u1 = u0 + 1;
            float v00 = fmaxf(acc1[n][0] + sbr1[u0] + b0.x*sW1t[u0] + b0.y*sW1t[64+u0], 0.f);
            float v01 = fmaxf(acc1[n][1] + sbr1[u1] + b0.x*sW1t[u1] + b0.y*sW1t[64+u1], 0.f);
            float v10 = fmaxf(acc1[n][2] + sbr1[u0] + b1.x*sW1t[u0] + b1.y*sW1t[64+u0], 0.f);
            float v11 = fmaxf(acc1[n][3] + sbr1[u1] + b1.x*sW1t[u1] + b1.y*sW1t[64+u1], 0.f);
            float h00 = bf16hi(v00), h01 = bf16hi(v01), h10 = bf16hi(v10), h11 = bf16hi(v11);
            int kk2 = n >> 1;
            int hi2 = (n & 1) ? 2 : 0;     // even n -> a0/a1, odd n -> a2/a3
            A2h[kk2][hi2+0] = bf16pack(v00, v01);
            A2h[kk2][hi2+1] = bf16pack(v10, v11);
            A2l[kk2][hi2+0] = bf16pack(v00 - h00, v01 - h01);
            A2l[kk2][hi2+1] = bf16pack(v10 - h10, v11 - h11);
        }
        // fix ordering: fragment is {a0,a1,a2,a3}; even n wrote slots 0,1; odd n slots 2,3 — correct.

        // ---- GEMM2: [16,64] x [64,128] hi/lo split ----
        float acc2[16][4];
        #pragma unroll
        for (int n = 0; n < 16; n++){ acc2[n][0]=0; acc2[n][1]=0; acc2[n][2]=0; acc2[n][3]=0; }
        #pragma unroll
        for (int kk = 0; kk < 4; kk++){
            uint32_t ahx = A2h[kk][0], ahy = A2h[kk][1], ahz = A2h[kk][2], ahw = A2h[kk][3];
            uint32_t alx = A2l[kk][0], aly = A2l[kk][1], alz = A2l[kk][2], alw = A2l[kk][3];
            #pragma unroll
            for (int n = 0; n < 16; n++){
                int bi = ((kk*16 + n)*32 + lane)*2;
                uint32_t bh0 = sB2h[bi], bh1 = sB2h[bi+1];
                uint32_t bl0 = sB2l[bi], bl1 = sB2l[bi+1];
                MMA_BF16(acc2[n], ahx, ahy, ahz, ahw, bh0, bh1);
                MMA_BF16(acc2[n], ahx, ahy, ahz, ahw, bl0, bl1);
                MMA_BF16(acc2[n], alx, aly, alz, alw, bh0, bh1);
            }
        }

        // ---- epilogue2: +br2 -> tbuf[edge][col] (stride 132) ----
        int rowA = w*16 + r0, rowB = rowA + 8;
        #pragma unroll
        for (int n = 0; n < 16; n++){
            int col = n*8 + cb;
            float bb0 = sbr2[col], bb1 = sbr2[col+1];
            *(float2*)(tbuf + rowA*132 + col) = make_float2(acc2[n][0] + bb0, acc2[n][1] + bb1);
            *(float2*)(tbuf + rowB*132 + col) = make_float2(acc2[n][2] + bb0, acc2[n][3] + bb1);
        }
        __syncwarp();

        // ---- fused tail: messages + logits (lane = channel) ----
        for (int j = 0; j < 16; j++){
            int el = w*16 + j;
            int eg = tt*64 + el;
            if (eg >= E) break;
            int s = esrc[eg], d = edst[eg];
            float rx = g_rhat[(size_t)eg*3+0];
            float ry = g_rhat[(size_t)eg*3+1];
            float rz = g_rhat[(size_t)eg*3+2];
            const float* trow = tbuf + el*132;
            float w00 = trow[lane], w01 = trow[32+lane], w10 = trow[64+lane], w11 = trow[96+lane];
            int sc = s*CV + lane;
            float gdot = g_g01x[sc]*rx + g_g01y[sc]*ry + g_g01z[sc]*rz;
            float kc = w00*g_a00[sc] + w01*gdot;
            size_t ec = (size_t)eg*CV + lane;
            g_k[ec]    = kc;
            g_s10[ec]  = w10*g_a10[sc];
            g_w11e[ec] = w11;
            float pq = g_q[d*CV+lane]*kc;
            pq += __shfl_down_sync(0xffffffffu, pq, 4);
            pq += __shfl_down_sync(0xffffffffu, pq, 2);
            pq += __shfl_down_sync(0xffffffffu, pq, 1);
            if ((lane & 7) == 0)
                g_logit[(size_t)eg*HV + (lane>>3)] = pq * 0.3535533906f;
        }
        __syncwarp();
    }
}

// ---- K4: softmax + aggregation + update + norms (+ fused pre/final) ----
__global__ void k_node_agg(const int* __restrict__ esrc,
                           const float* __restrict__ Wself0,
                           const float* __restrict__ Wself1,
                           const float* __restrict__ gamma0,
                           const float* __restrict__ beta0,
                           const float* __restrict__ gamma1,
                           const float* __restrict__ WqN,
                           const float* __restrict__ W00N,
                           const float* __restrict__ W10N,
                           const float* __restrict__ W01N,
                           const float* __restrict__ W11N,
                           int do_pre,
                           const float* __restrict__ Wout,
                           const float* __restrict__ coords,
                           float* __restrict__ out,
                           int do_final, int rb){
    __shared__ float sW0[1024], sW1[1024];
    __shared__ float sPq[1024], sP00[1024], sP10[1024], sP01[1024], sP11[1024];
    int tid = threadIdx.x;
    for (int i = tid; i < 1024; i += 256){ sW0[i] = Wself0[i]; sW1[i] = Wself1[i]; }
    if (do_pre){
        for (int i = tid; i < 1024; i += 256){
            sPq[i] = WqN[i]; sP00[i] = W00N[i]; sP10[i] = W10N[i];
            sP01[i] = W01N[i]; sP11[i] = W11N[i];
        }
    }
    __syncthreads();
    const float* g11rx = g_g11x[rb];
    const float* g11ry = g_g11y[rb];
    const float* g11rz = g_g11z[rb];
    float* g11wx = g_g11x[rb^1];
    float* g11wy = g_g11y[rb^1];
    float* g11wz = g_g11z[rb^1];
    int w = tid >> 5, lane = tid & 31;
    for (int n = blockIdx.x*8 + w; n < NNODE; n += gridDim.x*8){
        int rp = g_rowptr[n], deg = g_rowptr[n+1] - rp;
        float mx = -1e30f;
        for (int j0 = 0; j0 < deg; j0 += 8){
            int j = j0 + (lane >> 2);
            if (j < deg){
                int e = g_ceidx[rp + j];
                mx = fmaxf(mx, g_logit[(size_t)e*HV + (lane & 3)]);
            }
        }
        mx = fmaxf(mx, __shfl_xor_sync(0xffffffffu, mx, 4));
        mx = fmaxf(mx, __shfl_xor_sync(0xffffffffu, mx, 8));
        mx = fmaxf(mx, __shfl_xor_sync(0xffffffffu, mx, 16));
        if (mx < -1e29f) mx = 0.f;
        float den = 0.f;
        for (int j0 = 0; j0 < deg; j0 += 8){
            int j = j0 + (lane >> 2);
            if (j < deg){
                int e = g_ceidx[rp + j];
                den += expf(g_logit[(size_t)e*HV + (lane & 3)] - mx);
            }
        }
        den += __shfl_xor_sync(0xffffffffu, den, 4);
        den += __shfl_xor_sync(0xffffffffu, den, 8);
        den += __shfl_xor_sync(0xffffffffu, den, 16);
        float mxh  = __shfl_sync(0xffffffffu, mx,  lane >> 3);
        float dinv = 1.f / (__shfl_sync(0xffffffffu, den, lane >> 3) + 1e-9f);
        float a0=0.f, ax=0.f, ay=0.f, az=0.f;
        for (int j = 0; j < deg; j++){
            int e = g_ceidx[rp + j];
            float alpha = expf(g_logit[(size_t)e*HV + (lane>>3)] - mxh) * dinv;
            size_t ec = (size_t)e*CV + lane;
            float kc = g_k[ec];
            a0 += alpha * kc;
            float s10 = g_s10[ec], w11 = g_w11e[ec];
            float rx = g_rhat[(size_t)e*3+0];
            float ry = g_rhat[(size_t)e*3+1];
            float rz = g_rhat[(size_t)e*3+2];
            int s  = esrc[e];
            int sc = s*CV + lane;
            ax += alpha * (w11*g11rx[sc] + s10*rx);
            ay += alpha * (w11*g11ry[sc] + s10*ry);
            az += alpha * (w11*g11rz[sc] + s10*rz);
        }
        float nh0 = g_h0 [n*CV + lane];
        float x   = g_h1x[n*CV + lane];
        float y   = g_h1y[n*CV + lane];
        float z   = g_h1z[n*CV + lane];
        #pragma unroll 8
        for (int c = 0; c < CV; c++){
            float b0 = __shfl_sync(0xffffffffu, a0, c);
            float bx = __shfl_sync(0xffffffffu, ax, c);
            float by = __shfl_sync(0xffffffffu, ay, c);
            float bz = __shfl_sync(0xffffffffu, az, c);
            float w0 = sW0[c*CV+lane], w1 = sW1[c*CV+lane];
            nh0 += b0*w0;
            x += bx*w1; y += by*w1; z += bz*w1;
        }
        float mu  = warpsum(nh0) * (1.f/32.f);
        float dv  = nh0 - mu;
        float var = warpsum(dv*dv) * (1.f/32.f);
        float h0new = dv*rsqrtf(var + 1e-5f)*gamma0[lane] + beta0[lane];
        g_h0[n*CV+lane] = h0new;
        float nrm  = sqrtf(x*x + y*y + z*z + 1e-12f);
        float mun  = warpsum(nrm) * (1.f/32.f);
        float dn   = nrm - mun;
        float varn = warpsum(dn*dn) * (1.f/32.f);
        float nln  = dn*rsqrtf(varn + 1e-5f)*gamma1[lane];
        float sc   = nln / (nrm + 1e-8f);
        float hx = x*sc, hy = y*sc, hz = z*sc;
        g_h1x[n*CV+lane] = hx;
        g_h1y[n*CV+lane] = hy;
        g_h1z[n*CV+lane] = hz;

        if (do_pre){
            float q=0, p00=0, p10=0;
            float g01x=0,g01y=0,g01z=0,g11x=0,g11y=0,g11z=0;
            #pragma unroll 8
            for (int c = 0; c < CV; c++){
                float hc  = __shfl_sync(0xffffffffu, h0new, c);
                float hcx = __shfl_sync(0xffffffffu, hx, c);
                float hcy = __shfl_sync(0xffffffffu, hy, c);
                float hcz = __shfl_sync(0xffffffffu, hz, c);
                q   += hc*sPq [c*CV+lane];
                p00 += hc*sP00[c*CV+lane];
                p10 += hc*sP10[c*CV+lane];
                float w01 = sP01[c*CV+lane], w11 = sP11[c*CV+lane];
                g01x += hcx*w01; g01y += hcy*w01; g01z += hcz*w01;
                g11x += hcx*w11; g11y += hcy*w11; g11z += hcz*w11;
            }
            g_q  [n*CV+lane] = q;
            g_a00[n*CV+lane] = p00;
            g_a10[n*CV+lane] = p10;
            g_g01x[n*CV+lane]=g01x; g_g01y[n*CV+lane]=g01y; g_g01z[n*CV+lane]=g01z;
            g11wx[n*CV+lane]=g11x; g11wy[n*CV+lane]=g11y; g11wz[n*CV+lane]=g11z;
        }
        if (do_final){
            float wo = Wout[lane];
            float dx = warpsum(hx*wo);
            float dy = warpsum(hy*wo);
            float dz = warpsum(hz*wo);
            if (lane == 0){
                out[n*3+0] = coords[n*3+0] + dx;
                out[n*3+1] = coords[n*3+1] + dy;
                out[n*3+2] = coords[n*3+2] + dz;
            }
        }
    }
}

extern "C" void kernel_launch(void* const* d_in, const int* in_sizes, int n_in,
                              void* d_out, int out_size){
    const float* seq    = (const float*)d_in[0];
    const float* pair   = (const float*)d_in[1];
    const float* bppm   = (const float*)d_in[2];
    const float* coords = (const float*)d_in[3];
    const int*   esrc   = (const int*)  d_in[4];
    const int*   edst   = (const int*)  d_in[5];
    const float* Win0   = (const float*)d_in[6];
    const float* Win1   = (const float*)d_in[7];
    const float* Wr1    = (const float*)d_in[8];
    const float* br1    = (const float*)d_in[9];
    const float* Wr2    = (const float*)d_in[10];
    const float* br2    = (const float*)d_in[11];
    const float* Wm00   = (const float*)d_in[12];
    const float* Wm01   = (const float*)d_in[13];
    const float* Wm10   = (const float*)d_in[14];
    const float* Wm11   = (const float*)d_in[15];
    const float* Wq     = (const float*)d_in[16];
    const float* Wself0 = (const float*)d_in[17];
    const float* Wself1 = (const float*)d_in[18];
    const float* gamma0 = (const float*)d_in[19];
    const float* beta0  = (const float*)d_in[20];
    const float* gamma1 = (const float*)d_in[21];
    const float* Wout   = (const float*)d_in[22];

    int E = in_sizes[4];
    if (E > EMAX) E = EMAX;

    cudaFuncSetAttribute(k_mma_pass1,
        cudaFuncAttributeMaxDynamicSharedMemorySize, SM_BYTES);
    cudaFuncSetAttribute(k_init_nodes,
        cudaFuncAttributeMaxDynamicSharedMemorySize, (20480+16*D0V)*4);

    // pass1 (layer 0) is launch #4 -> ncu captures it
    k_init_nodes<<<128, 512, (20480+16*D0V)*4>>>(seq, coords, Win0, Win1);
    k_edge_setup<<<1480, 256>>>(coords, pair, bppm, esrc, edst, E);
    k_node_pre<<<128, 256>>>(Wq, Wm00, Wm10, Wm01, Wm11);
    k_mma_pass1<<<296, 128, SM_BYTES>>>(esrc, edst, Wr1, br1, Wr2, br2, E);

    k_scan<<<1, 1024>>>(E);
    k_fill<<<(E+255)/256, 256>>>(edst, E);

    for (int l = 0; l < NLV; l++){
        int lp = l + 1;
        int rb = l & 1;
        int do_pre = (l < NLV-1);
        int do_fin = (l == NLV-1);
        if (l > 0)
            k_mma_pass1<<<296, 128, SM_BYTES>>>(esrc, edst,
                Wr1 + l*RADIN*HIDV, br1 + l*HIDV, Wr2 + l*HIDV*R4C, br2 + l*R4C, E);
        k_node_agg<<<256, 256>>>(esrc,
            Wself0 + l*CV*CV, Wself1 + l*CV*CV,
            gamma0 + l*CV, beta0 + l*CV, gamma1 + l*CV,
            Wq + (do_pre ? lp*CV*CV : 0), Wm00 + (do_pre ? lp*CV*CV : 0),
            Wm10 + (do_pre ? lp*CV*CV : 0), Wm01 + (do_pre ? lp*CV*CV : 0),
            Wm11 + (do_pre ? lp*CV*CV : 0), do_pre,
            Wout, coords, (float*)d_out, do_fin, rb);
    }
}